// round 1
// baseline (speedup 1.0000x reference)
#include <cuda_runtime.h>
#include <math.h>

#define NN 50000
#define DD 200
#define RR 480
#define TT 4
#define EE 100000
#define SLOPE 0.22916666666666666f

// ---------------- scratch (device globals; no allocations) ----------------
__device__ float g_h[NN * DD];     // entity state h
__device__ float g_hhA[NN * DD];   // layer ping
__device__ float g_hhB[NN * DD];   // layer pong / cur
__device__ float g_agg[NN * DD];   // neighbor aggregation
__device__ float g_norm[NN];       // deg -> 1/max(deg,1)
__device__ float g_h0[RR * DD];    // relation state
__device__ float g_ssum[RR * DD];  // per-relation sum
__device__ float g_cnt[RR];        // per-relation count

// ---------------- small utility kernels ----------------
__global__ void k_zero(float* __restrict__ p, int n) {
    int i = blockIdx.x * blockDim.x + threadIdx.x;
    if (i < n) p[i] = 0.f;
}

__global__ void k_copy(const float* __restrict__ in, float* __restrict__ out, int n) {
    int i = blockIdx.x * blockDim.x + threadIdx.x;
    if (i < n) out[i] = in[i];
}

// one warp per row: out = row / max(||row||, 1e-12)
__global__ void k_l2norm_rows(const float* __restrict__ in, float* __restrict__ out, int nrows) {
    int w = (blockIdx.x * blockDim.x + threadIdx.x) >> 5;
    int lane = threadIdx.x & 31;
    if (w >= nrows) return;
    const float* r = in + (size_t)w * DD;
    float ss = 0.f;
    for (int d = lane; d < DD; d += 32) { float v = r[d]; ss += v * v; }
    #pragma unroll
    for (int o = 16; o; o >>= 1) ss += __shfl_xor_sync(0xffffffffu, ss, o);
    float s = 1.f / fmaxf(sqrtf(ss), 1e-12f);
    float* po = out + (size_t)w * DD;
    for (int d = lane; d < DD; d += 32) po[d] = r[d] * s;
}

// ---------------- relation mean scatter ----------------
// for j in [0, 2E): ent = j<E ? src[j] : dst[j-E]; rel = etype[j % E]
// ssum[rel] += h[ent];  cnt[rel] += 1 (once per j)
__global__ void k_rel_scatter(const int* __restrict__ src, const int* __restrict__ dst,
                              const int* __restrict__ et) {
    int idx = blockIdx.x * blockDim.x + threadIdx.x;
    if (idx >= 2 * EE * DD) return;
    int j = idx / DD;
    int d = idx - j * DD;
    int e = (j < EE) ? j : j - EE;
    int ent = (j < EE) ? src[e] : dst[e];
    int r = et[e];
    atomicAdd(&g_ssum[r * DD + d], g_h[ent * DD + d]);
    if (d == 0) atomicAdd(&g_cnt[r], 1.f);
}

// ---------------- GRU on relations (one block per relation) ----------------
__global__ void k_gru(const float* __restrict__ emb_rel, const float* __restrict__ W_ih,
                      const float* __restrict__ W_hh, const float* __restrict__ b_ih,
                      const float* __restrict__ b_hh) {
    __shared__ float sx[2 * DD];   // x_input row: [emb_rel | x_mean]
    __shared__ float shp[DD];      // h0 prev
    __shared__ float sgi[3 * DD];
    __shared__ float sgh[3 * DD];
    __shared__ float shn[DD];
    __shared__ float sred[256];
    int r = blockIdx.x;
    int tid = threadIdx.x;
    float inv_cnt = 1.f / fmaxf(g_cnt[r], 1.f);
    for (int d = tid; d < DD; d += 256) {
        sx[d] = emb_rel[r * DD + d];
        sx[DD + d] = g_ssum[r * DD + d] * inv_cnt;
        shp[d] = g_h0[r * DD + d];
    }
    __syncthreads();
    for (int j = tid; j < 3 * DD; j += 256) {
        const float* wi = W_ih + (size_t)j * (2 * DD);
        float a = b_ih[j];
        #pragma unroll 4
        for (int k = 0; k < 2 * DD; ++k) a = fmaf(sx[k], wi[k], a);
        sgi[j] = a;
        const float* wh = W_hh + (size_t)j * DD;
        float b = b_hh[j];
        #pragma unroll 4
        for (int k = 0; k < DD; ++k) b = fmaf(shp[k], wh[k], b);
        sgh[j] = b;
    }
    __syncthreads();
    float ss = 0.f;
    for (int d = tid; d < DD; d += 256) {
        float rg = 1.f / (1.f + expf(-(sgi[d] + sgh[d])));
        float zg = 1.f / (1.f + expf(-(sgi[DD + d] + sgh[DD + d])));
        float ng = tanhf(sgi[2 * DD + d] + rg * sgh[2 * DD + d]);
        float hn = (1.f - zg) * ng + zg * shp[d];
        shn[d] = hn;
        ss += hn * hn;
    }
    sred[tid] = ss;
    __syncthreads();
    #pragma unroll
    for (int o = 128; o; o >>= 1) {
        if (tid < o) sred[tid] += sred[tid + o];
        __syncthreads();
    }
    float s = 1.f / fmaxf(sqrtf(sred[0]), 1e-12f);
    for (int d = tid; d < DD; d += 256) g_h0[r * DD + d] = shn[d] * s;
}

// ---------------- degree ----------------
__global__ void k_deg(const int* __restrict__ dst) {
    int e = blockIdx.x * blockDim.x + threadIdx.x;
    if (e < EE) atomicAdd(&g_norm[dst[e]], 1.f);
}
__global__ void k_degnorm() {
    int i = blockIdx.x * blockDim.x + threadIdx.x;
    if (i < NN) g_norm[i] = 1.f / fmaxf(g_norm[i], 1.f);
}

// ---------------- edge message scatter: agg[dst] += hh[src] + h0[et] ----------------
__global__ void k_edge(const int* __restrict__ src, const int* __restrict__ dst,
                       const int* __restrict__ et, const float* __restrict__ hh) {
    int idx = blockIdx.x * blockDim.x + threadIdx.x;
    if (idx >= EE * DD) return;
    int e = idx / DD;
    int d = idx - e * DD;
    int s = src[e], dn = dst[e], r = et[e];
    atomicAdd(&g_agg[dn * DD + d], hh[s * DD + d] + g_h0[r * DD + d]);
}

// ---------------- fused RGCN GEMM ----------------
// out = rrelu( norm[row]*(agg @ Wn) + hh @ Wl ), 50000x200, virtual K=400
// BM=128 rows, full 200 cols, BK=8. 256 thr: tx=tid&7 (col), ty=tid>>3 (row),
// each thread: 4 rows (ty+32*rr) x 25 cols (tx+8*cc).
__global__ void __launch_bounds__(256, 1)
k_rgcn_gemm(const float* __restrict__ hhin, const float* __restrict__ Wn,
            const float* __restrict__ Wl, float* __restrict__ out) {
    __shared__ float sA[128][9];
    __shared__ float sW[8][200];
    int tid = threadIdx.x;
    int tx = tid & 7;
    int ty = tid >> 3;
    int row0 = blockIdx.x * 128;
    float acc[4][25];
    #pragma unroll
    for (int rr = 0; rr < 4; ++rr)
        #pragma unroll
        for (int cc = 0; cc < 25; ++cc) acc[rr][cc] = 0.f;

    for (int p = 0; p < 2; ++p) {
        const float* A = p ? hhin : g_agg;
        const float* W = p ? Wl : Wn;
        for (int k0 = 0; k0 < DD; k0 += 8) {
            // load A tile 128x8
            #pragma unroll
            for (int i = 0; i < 4; ++i) {
                int idx = tid + i * 256;      // 0..1023
                int r = idx >> 3;
                int kk = idx & 7;
                int row = row0 + r;
                float v = 0.f;
                if (row < NN) {
                    v = A[(size_t)row * DD + k0 + kk];
                    if (p == 0) v *= g_norm[row];
                }
                sA[r][kk] = v;
            }
            // load W tile 8x200
            for (int idx = tid; idx < 8 * DD; idx += 256) {
                int kk = idx / DD;
                int c = idx - kk * DD;
                sW[kk][c] = W[(size_t)(k0 + kk) * DD + c];
            }
            __syncthreads();
            #pragma unroll
            for (int kk = 0; kk < 8; ++kk) {
                float a[4];
                #pragma unroll
                for (int rr = 0; rr < 4; ++rr) a[rr] = sA[ty + 32 * rr][kk];
                #pragma unroll
                for (int cc = 0; cc < 25; ++cc) {
                    float w = sW[kk][tx + 8 * cc];
                    #pragma unroll
                    for (int rr = 0; rr < 4; ++rr) acc[rr][cc] = fmaf(a[rr], w, acc[rr][cc]);
                }
            }
            __syncthreads();
        }
    }
    #pragma unroll
    for (int rr = 0; rr < 4; ++rr) {
        int row = row0 + ty + 32 * rr;
        if (row >= NN) continue;
        #pragma unroll
        for (int cc = 0; cc < 25; ++cc) {
            int c = tx + 8 * cc;
            float v = acc[rr][cc];
            out[(size_t)row * DD + c] = (v >= 0.f) ? v : v * SLOPE;
        }
    }
}

// ---------------- time gate GEMM ----------------
// tw = sigmoid(h @ Wt + bt); hn = tw*cur + (1-tw)*h; g_h = hn; hist = hn
__global__ void __launch_bounds__(256, 1)
k_timegate(const float* __restrict__ Wt, const float* __restrict__ bt,
           float* __restrict__ hist) {
    __shared__ float sA[128][9];
    __shared__ float sW[8][200];
    int tid = threadIdx.x;
    int tx = tid & 7;
    int ty = tid >> 3;
    int row0 = blockIdx.x * 128;
    float acc[4][25];
    #pragma unroll
    for (int rr = 0; rr < 4; ++rr)
        #pragma unroll
        for (int cc = 0; cc < 25; ++cc) acc[rr][cc] = 0.f;

    for (int k0 = 0; k0 < DD; k0 += 8) {
        #pragma unroll
        for (int i = 0; i < 4; ++i) {
            int idx = tid + i * 256;
            int r = idx >> 3;
            int kk = idx & 7;
            int row = row0 + r;
            sA[r][kk] = (row < NN) ? g_h[(size_t)row * DD + k0 + kk] : 0.f;
        }
        for (int idx = tid; idx < 8 * DD; idx += 256) {
            int kk = idx / DD;
            int c = idx - kk * DD;
            sW[kk][c] = Wt[(size_t)(k0 + kk) * DD + c];
        }
        __syncthreads();
        #pragma unroll
        for (int kk = 0; kk < 8; ++kk) {
            float a[4];
            #pragma unroll
            for (int rr = 0; rr < 4; ++rr) a[rr] = sA[ty + 32 * rr][kk];
            #pragma unroll
            for (int cc = 0; cc < 25; ++cc) {
                float w = sW[kk][tx + 8 * cc];
                #pragma unroll
                for (int rr = 0; rr < 4; ++rr) acc[rr][cc] = fmaf(a[rr], w, acc[rr][cc]);
            }
        }
        __syncthreads();
    }
    #pragma unroll
    for (int rr = 0; rr < 4; ++rr) {
        int row = row0 + ty + 32 * rr;
        if (row >= NN) continue;
        #pragma unroll
        for (int cc = 0; cc < 25; ++cc) {
            int c = tx + 8 * cc;
            float tw = 1.f / (1.f + expf(-(acc[rr][cc] + bt[c])));
            size_t off = (size_t)row * DD + c;
            float hold = g_h[off];
            float hn = tw * g_hhB[off] + (1.f - tw) * hold;
            g_h[off] = hn;
            hist[off] = hn;
        }
    }
}

// ---------------- host driver ----------------
extern "C" void kernel_launch(void* const* d_in, const int* in_sizes, int n_in,
                              void* d_out, int out_size) {
    const int* src = (const int*)d_in[0];
    const int* dst = (const int*)d_in[1];
    const int* et  = (const int*)d_in[2];
    const float* dyn     = (const float*)d_in[3];
    const float* emb_rel = (const float*)d_in[4];
    const float* W_ih    = (const float*)d_in[5];
    const float* W_hh    = (const float*)d_in[6];
    const float* b_ih    = (const float*)d_in[7];
    const float* b_hh    = (const float*)d_in[8];
    const float* W_nb    = (const float*)d_in[9];
    const float* W_lp    = (const float*)d_in[10];
    const float* Wt      = (const float*)d_in[11];
    const float* bt      = (const float*)d_in[12];
    float* out = (float*)d_out;

    float *p_h, *p_hhA, *p_hhB, *p_agg, *p_norm, *p_h0, *p_ssum, *p_cnt;
    cudaGetSymbolAddress((void**)&p_h,    g_h);
    cudaGetSymbolAddress((void**)&p_hhA,  g_hhA);
    cudaGetSymbolAddress((void**)&p_hhB,  g_hhB);
    cudaGetSymbolAddress((void**)&p_agg,  g_agg);
    cudaGetSymbolAddress((void**)&p_norm, g_norm);
    cudaGetSymbolAddress((void**)&p_h0,   g_h0);
    cudaGetSymbolAddress((void**)&p_ssum, g_ssum);
    cudaGetSymbolAddress((void**)&p_cnt,  g_cnt);

    const int gemm_blocks = (NN + 127) / 128;  // 391

    // init: h = l2norm(dynamic_emb); h0 = emb_rel
    k_l2norm_rows<<<(NN * 32 + 255) / 256, 256>>>(dyn, p_h, NN);
    k_copy<<<(RR * DD + 255) / 256, 256>>>(emb_rel, p_h0, RR * DD);

    for (int t = 0; t < TT; ++t) {
        const int* s_t = src + t * EE;
        const int* d_t = dst + t * EE;
        const int* e_t = et  + t * EE;

        // relation mean + GRU update of h0
        k_zero<<<(RR * DD + 255) / 256, 256>>>(p_ssum, RR * DD);
        k_zero<<<(RR + 255) / 256, 256>>>(p_cnt, RR);
        k_rel_scatter<<<(2 * EE * DD + 255) / 256, 256>>>(s_t, d_t, e_t);
        k_gru<<<RR, 256>>>(emb_rel, W_ih, W_hh, b_ih, b_hh);

        // degrees -> norm
        k_zero<<<(NN + 255) / 256, 256>>>(p_norm, NN);
        k_deg<<<(EE + 255) / 256, 256>>>(d_t);
        k_degnorm<<<(NN + 255) / 256, 256>>>();

        // layer 0: h -> hhA
        k_zero<<<(NN * DD + 255) / 256, 256>>>(p_agg, NN * DD);
        k_edge<<<(EE * DD + 255) / 256, 256>>>(s_t, d_t, e_t, p_h);
        k_rgcn_gemm<<<gemm_blocks, 256>>>(p_h, W_nb, W_lp, p_hhA);

        // layer 1: hhA -> hhB
        k_zero<<<(NN * DD + 255) / 256, 256>>>(p_agg, NN * DD);
        k_edge<<<(EE * DD + 255) / 256, 256>>>(s_t, d_t, e_t, p_hhA);
        k_rgcn_gemm<<<gemm_blocks, 256>>>(p_hhA, W_nb + DD * DD, W_lp + DD * DD, p_hhB);

        // cur = l2norm(hhB) in place
        k_l2norm_rows<<<(NN * 32 + 255) / 256, 256>>>(p_hhB, p_hhB, NN);

        // time gate: updates g_h and writes hist[t]
        k_timegate<<<gemm_blocks, 256>>>(Wt, bt, out + (size_t)t * NN * DD);
    }
}

// round 3
// speedup vs baseline: 3.4390x; 3.4390x over previous
#include <cuda_runtime.h>
#include <cstdint>
#include <math.h>

#define NN 50000
#define DD 200
#define RR 480
#define TT 4
#define EE 100000
#define SLOPE 0.22916666666666666f

// ---------------- device scratch (no allocations) ----------------
__device__ float g_h[NN * DD];
__device__ float g_hhA[NN * DD];
__device__ float g_hhB[NN * DD];
__device__ float g_agg[NN * DD];
__device__ float g_norm[NN];
__device__ float g_h0[RR * DD];
__device__ float g_ssum[RR * DD];
__device__ float g_cnt[RR];
__device__ float g_Bt[5 * DD * DD + 4096];  // transposed weights + OOB pad

// ---------------- helpers ----------------
__device__ __forceinline__ uint32_t smem_u32(const void* p) {
    uint32_t a;
    asm("{ .reg .u64 t; cvta.to.shared.u64 t, %1; cvt.u32.u64 %0, t; }" : "=r"(a) : "l"(p));
    return a;
}

#define CP16(sm_addr, gptr) \
    asm volatile("cp.async.ca.shared.global [%0], [%1], 16;" :: "r"(sm_addr), "l"(gptr))
#define CP_COMMIT() asm volatile("cp.async.commit_group;" ::: "memory")
#define CP_WAIT1()  asm volatile("cp.async.wait_group 1;" ::: "memory")
#define CP_WAIT0()  asm volatile("cp.async.wait_group 0;" ::: "memory")

#define MMA_TF32(d, a, b0, b1)                                                    \
    asm volatile("mma.sync.aligned.m16n8k8.row.col.f32.tf32.tf32.f32 "            \
                 "{%0,%1,%2,%3}, {%4,%5,%6,%7}, {%8,%9}, {%0,%1,%2,%3};"          \
                 : "+f"((d)[0]), "+f"((d)[1]), "+f"((d)[2]), "+f"((d)[3])         \
                 : "r"((a)[0]), "r"((a)[1]), "r"((a)[2]), "r"((a)[3]),            \
                   "r"(b0), "r"(b1))

__device__ __forceinline__ void red_add_v4(float* p, float4 v) {
    asm volatile("red.global.add.v4.f32 [%0], {%1, %2, %3, %4};"
                 :: "l"(p), "f"(v.x), "f"(v.y), "f"(v.z), "f"(v.w) : "memory");
}

// ---------------- fused tensor-core GEMM (mma.sync tf32) ----------------
// acc[128,200] = sum_parts Apart @ Bpart^T; optional norm row-scale on part 0.
// mode 0: out = rrelu(acc). mode 1: tw=sigmoid(acc+bt); h=tw*cur+(1-tw)*h; hist=h.
// smem stage: A rows stride 12 floats (row r: k at r*12+k), B rows 1536 + n*12+k.
__global__ void __launch_bounds__(256)
k_mma_gemm(const float* __restrict__ A0, const float* __restrict__ A1,
           const float* __restrict__ B0g, const float* __restrict__ B1g,
           const float* __restrict__ normv, float* __restrict__ outp,
           const float* __restrict__ bt, const float* __restrict__ curv,
           float* __restrict__ hstate, float* __restrict__ hist,
           int mode, int nparts) {
    __shared__ __align__(16) float sm[2][4032];  // 1536 A + 2496 B per stage
    int tid = threadIdx.x, lane = tid & 31, wid = tid >> 5;
    int wr = wid >> 1, wc = wid & 1;
    int row0 = blockIdx.x * 128;

    float acc[2][13][4];
    #pragma unroll
    for (int mt = 0; mt < 2; ++mt)
        #pragma unroll
        for (int nt = 0; nt < 13; ++nt)
            #pragma unroll
            for (int q = 0; q < 4; ++q) acc[mt][nt][q] = 0.f;

    const int nk = nparts * 25;

    // ---- async stage loader ----
    auto issue = [&](int c) {
        const float* A = (c < 25) ? A0 : A1;
        const float* B = (c < 25) ? B0g : B1g;
        int k0 = ((c < 25) ? c : c - 25) * 8;
        int buf = c & 1;
        {   // A tile: 128 rows x 8 floats, one 16B chunk per thread
            int r = tid >> 1, h = tid & 1;
            int row = row0 + r;
            if (row >= NN) row = NN - 1;
            uint32_t sa = smem_u32(&sm[buf][r * 12 + h * 4]);
            CP16(sa, A + (size_t)row * DD + k0 + h * 4);
        }
        // B tile: 208 rows x 8 floats (rows >=200 read pad garbage, cols discarded)
        #pragma unroll
        for (int j = tid; j < 416; j += 256) {
            int n = j >> 1, h = j & 1;
            uint32_t sb = smem_u32(&sm[buf][1536 + n * 12 + h * 4]);
            CP16(sb, B + (size_t)n * DD + k0 + h * 4);
        }
        CP_COMMIT();
    };

    issue(0);
    for (int c = 0; c < nk; ++c) {
        if (c + 1 < nk) { issue(c + 1); CP_WAIT1(); } else { CP_WAIT0(); }
        __syncthreads();
        int buf = c & 1;
        // A fragments (2 m-tiles)
        uint32_t a[2][4];
        int rb = wr * 32 + (lane >> 2);
        int kk = lane & 3;
        #pragma unroll
        for (int mt = 0; mt < 2; ++mt) {
            int r = rb + mt * 16;
            a[mt][0] = __float_as_uint(sm[buf][r * 12 + kk]);
            a[mt][1] = __float_as_uint(sm[buf][(r + 8) * 12 + kk]);
            a[mt][2] = __float_as_uint(sm[buf][r * 12 + kk + 4]);
            a[mt][3] = __float_as_uint(sm[buf][(r + 8) * 12 + kk + 4]);
        }
        int nb = wc * 104 + (lane >> 2);
        #pragma unroll
        for (int nt = 0; nt < 13; ++nt) {
            int n = nb + nt * 8;
            uint32_t b0 = __float_as_uint(sm[buf][1536 + n * 12 + kk]);
            uint32_t b1 = __float_as_uint(sm[buf][1536 + n * 12 + kk + 4]);
            MMA_TF32(acc[0][nt], a[0], b0, b1);
            MMA_TF32(acc[1][nt], a[1], b0, b1);
        }
        // end of part 0: apply per-row norm to accumulators
        if (c == 24 && nparts == 2 && normv != nullptr) {
            #pragma unroll
            for (int mt = 0; mt < 2; ++mt) {
                int r = row0 + wr * 32 + mt * 16 + (lane >> 2);
                int r2 = r + 8;
                float n0 = normv[r < NN ? r : NN - 1];
                float n1 = normv[r2 < NN ? r2 : NN - 1];
                #pragma unroll
                for (int nt = 0; nt < 13; ++nt) {
                    acc[mt][nt][0] *= n0; acc[mt][nt][1] *= n0;
                    acc[mt][nt][2] *= n1; acc[mt][nt][3] *= n1;
                }
            }
        }
        __syncthreads();
    }

    // ---- epilogue ----
    #pragma unroll
    for (int mt = 0; mt < 2; ++mt) {
        int r = row0 + wr * 32 + mt * 16 + (lane >> 2);
        #pragma unroll
        for (int nt = 0; nt < 13; ++nt) {
            int col = wc * 104 + nt * 8 + (lane & 3) * 2;
            if (col >= DD) continue;
            #pragma unroll
            for (int half = 0; half < 2; ++half) {
                int row = r + half * 8;
                if (row >= NN) continue;
                float v0 = acc[mt][nt][half * 2];
                float v1 = acc[mt][nt][half * 2 + 1];
                size_t off = (size_t)row * DD + col;
                if (mode == 0) {
                    float2 o;
                    o.x = (v0 >= 0.f) ? v0 : v0 * SLOPE;
                    o.y = (v1 >= 0.f) ? v1 : v1 * SLOPE;
                    *(float2*)&outp[off] = o;
                } else {
                    float t0 = 1.f / (1.f + expf(-(v0 + bt[col])));
                    float t1 = 1.f / (1.f + expf(-(v1 + bt[col + 1])));
                    float2 cu = *(const float2*)&curv[off];
                    float2 ho = *(const float2*)&hstate[off];
                    float2 hn;
                    hn.x = t0 * cu.x + (1.f - t0) * ho.x;
                    hn.y = t1 * cu.y + (1.f - t1) * ho.y;
                    *(float2*)&hstate[off] = hn;
                    *(float2*)&hist[off] = hn;
                }
            }
        }
    }
}

// ---------------- utility kernels ----------------
__global__ void k_copy(const float* __restrict__ in, float* __restrict__ out, int n) {
    int i = blockIdx.x * blockDim.x + threadIdx.x;
    if (i < n) out[i] = in[i];
}
__global__ void k_transpose(const float* __restrict__ W, float* __restrict__ Bt) {
    int idx = blockIdx.x * blockDim.x + threadIdx.x;
    if (idx < DD * DD) {
        int k = idx / DD, n = idx - k * DD;
        Bt[n * DD + k] = W[idx];
    }
}
__global__ void k_l2norm_rows(const float* __restrict__ in, float* __restrict__ out, int nrows) {
    int w = (blockIdx.x * blockDim.x + threadIdx.x) >> 5;
    int lane = threadIdx.x & 31;
    if (w >= nrows) return;
    const float* r = in + (size_t)w * DD;
    float ss = 0.f;
    for (int d = lane; d < DD; d += 32) { float v = r[d]; ss += v * v; }
    #pragma unroll
    for (int o = 16; o; o >>= 1) ss += __shfl_xor_sync(0xffffffffu, ss, o);
    float s = 1.f / fmaxf(sqrtf(ss), 1e-12f);
    float* po = out + (size_t)w * DD;
    for (int d = lane; d < DD; d += 32) po[d] = r[d] * s;
}

// ssum[et] += h[src] + h[dst] (v4 reductions); cnt[et] += 2
__global__ void k_rel_scatter(const int* __restrict__ src, const int* __restrict__ dst,
                              const int* __restrict__ et) {
    int idx = blockIdx.x * blockDim.x + threadIdx.x;
    if (idx >= EE * 50) return;
    int e = idx / 50, q = idx - e * 50;
    int s = src[e], d_ = dst[e], r = et[e];
    float4 a = *(const float4*)&g_h[(size_t)s * DD + q * 4];
    float4 b = *(const float4*)&g_h[(size_t)d_ * DD + q * 4];
    float4 v = make_float4(a.x + b.x, a.y + b.y, a.z + b.z, a.w + b.w);
    red_add_v4(&g_ssum[(size_t)r * DD + q * 4], v);
    if (q == 0) atomicAdd(&g_cnt[r], 2.f);
}

// agg[dst] += hh[src] + h0[et]
__global__ void k_edge(const int* __restrict__ src, const int* __restrict__ dst,
                       const int* __restrict__ et, const float* __restrict__ hh) {
    int idx = blockIdx.x * blockDim.x + threadIdx.x;
    if (idx >= EE * 50) return;
    int e = idx / 50, q = idx - e * 50;
    int s = src[e], dn = dst[e], r = et[e];
    float4 a = *(const float4*)&hh[(size_t)s * DD + q * 4];
    float4 b = *(const float4*)&g_h0[(size_t)r * DD + q * 4];
    float4 v = make_float4(a.x + b.x, a.y + b.y, a.z + b.z, a.w + b.w);
    red_add_v4(&g_agg[(size_t)dn * DD + q * 4], v);
}

__global__ void k_deg(const int* __restrict__ dst) {
    int e = blockIdx.x * blockDim.x + threadIdx.x;
    if (e < EE) atomicAdd(&g_norm[dst[e]], 1.f);
}
__global__ void k_degnorm() {
    int i = blockIdx.x * blockDim.x + threadIdx.x;
    if (i < NN) g_norm[i] = 1.f / fmaxf(g_norm[i], 1.f);
}

// ---------------- GRU (warp-per-output-row, coalesced W loads) ----------------
__global__ void k_gru(const float* __restrict__ emb_rel, const float* __restrict__ W_ih,
                      const float* __restrict__ W_hh, const float* __restrict__ b_ih,
                      const float* __restrict__ b_hh) {
    __shared__ float sx[2 * DD];
    __shared__ float shp[DD];
    __shared__ float sgi[3 * DD];
    __shared__ float sgh[3 * DD];
    __shared__ float shn[DD];
    __shared__ float sred[8];
    int r = blockIdx.x, tid = threadIdx.x, lane = tid & 31, wid = tid >> 5;
    float inv_cnt = 1.f / fmaxf(g_cnt[r], 1.f);
    for (int d = tid; d < DD; d += 256) {
        sx[d] = emb_rel[r * DD + d];
        sx[DD + d] = g_ssum[r * DD + d] * inv_cnt;
        shp[d] = g_h0[r * DD + d];
    }
    __syncthreads();
    for (int j = wid; j < 3 * DD; j += 8) {
        const float* wi = W_ih + (size_t)j * (2 * DD);
        float a = 0.f;
        for (int k = lane; k < 2 * DD; k += 32) a = fmaf(sx[k], wi[k], a);
        const float* wh = W_hh + (size_t)j * DD;
        float b = 0.f;
        for (int k = lane; k < DD; k += 32) b = fmaf(shp[k], wh[k], b);
        #pragma unroll
        for (int o = 16; o; o >>= 1) {
            a += __shfl_xor_sync(0xffffffffu, a, o);
            b += __shfl_xor_sync(0xffffffffu, b, o);
        }
        if (lane == 0) { sgi[j] = a + b_ih[j]; sgh[j] = b + b_hh[j]; }
    }
    __syncthreads();
    float ss = 0.f;
    for (int d = tid; d < DD; d += 256) {
        float rg = 1.f / (1.f + expf(-(sgi[d] + sgh[d])));
        float zg = 1.f / (1.f + expf(-(sgi[DD + d] + sgh[DD + d])));
        float ng = tanhf(sgi[2 * DD + d] + rg * sgh[2 * DD + d]);
        float hn = (1.f - zg) * ng + zg * shp[d];
        shn[d] = hn;
        ss += hn * hn;
    }
    #pragma unroll
    for (int o = 16; o; o >>= 1) ss += __shfl_xor_sync(0xffffffffu, ss, o);
    if (lane == 0) sred[wid] = ss;
    __syncthreads();
    if (tid == 0) {
        float t = 0.f;
        #pragma unroll
        for (int i = 0; i < 8; ++i) t += sred[i];
        sred[0] = t;
    }
    __syncthreads();
    float s = 1.f / fmaxf(sqrtf(sred[0]), 1e-12f);
    for (int d = tid; d < DD; d += 256) g_h0[r * DD + d] = shn[d] * s;
}

// ---------------- host driver ----------------
extern "C" void kernel_launch(void* const* d_in, const int* in_sizes, int n_in,
                              void* d_out, int out_size) {
    const int* src = (const int*)d_in[0];
    const int* dst = (const int*)d_in[1];
    const int* et  = (const int*)d_in[2];
    const float* dyn     = (const float*)d_in[3];
    const float* emb_rel = (const float*)d_in[4];
    const float* W_ih    = (const float*)d_in[5];
    const float* W_hh    = (const float*)d_in[6];
    const float* b_ih    = (const float*)d_in[7];
    const float* b_hh    = (const float*)d_in[8];
    const float* W_nb    = (const float*)d_in[9];
    const float* W_lp    = (const float*)d_in[10];
    const float* Wt      = (const float*)d_in[11];
    const float* bt      = (const float*)d_in[12];
    float* out = (float*)d_out;

    float *p_h, *p_hhA, *p_hhB, *p_agg, *p_norm, *p_h0, *p_ssum, *p_cnt, *p_Bt;
    cudaGetSymbolAddress((void**)&p_h,    g_h);
    cudaGetSymbolAddress((void**)&p_hhA,  g_hhA);
    cudaGetSymbolAddress((void**)&p_hhB,  g_hhB);
    cudaGetSymbolAddress((void**)&p_agg,  g_agg);
    cudaGetSymbolAddress((void**)&p_norm, g_norm);
    cudaGetSymbolAddress((void**)&p_h0,   g_h0);
    cudaGetSymbolAddress((void**)&p_ssum, g_ssum);
    cudaGetSymbolAddress((void**)&p_cnt,  g_cnt);
    cudaGetSymbolAddress((void**)&p_Bt,   g_Bt);

    const int gemm_blocks = (NN + 127) / 128;  // 391
    const int tb = (DD * DD + 255) / 256;
    const int eb = (EE * 50 + 255) / 256;

    // transposed weights: [0]=Wn0^T [1]=Wl0^T [2]=Wn1^T [3]=Wl1^T [4]=Wt^T
    k_transpose<<<tb, 256>>>(W_nb,           p_Bt + 0 * DD * DD);
    k_transpose<<<tb, 256>>>(W_lp,           p_Bt + 1 * DD * DD);
    k_transpose<<<tb, 256>>>(W_nb + DD * DD, p_Bt + 2 * DD * DD);
    k_transpose<<<tb, 256>>>(W_lp + DD * DD, p_Bt + 3 * DD * DD);
    k_transpose<<<tb, 256>>>(Wt,             p_Bt + 4 * DD * DD);

    // init: h = l2norm(dynamic_emb); h0 = emb_rel
    k_l2norm_rows<<<(NN * 32 + 255) / 256, 256>>>(dyn, p_h, NN);
    k_copy<<<(RR * DD + 255) / 256, 256>>>(emb_rel, p_h0, RR * DD);

    for (int t = 0; t < TT; ++t) {
        const int* s_t = src + t * EE;
        const int* d_t = dst + t * EE;
        const int* e_t = et  + t * EE;

        // relation mean + GRU update of h0
        cudaMemsetAsync(p_ssum, 0, RR * DD * sizeof(float));
        cudaMemsetAsync(p_cnt,  0, RR * sizeof(float));
        k_rel_scatter<<<eb, 256>>>(s_t, d_t, e_t);
        k_gru<<<RR, 256>>>(emb_rel, W_ih, W_hh, b_ih, b_hh);

        // degrees -> norm
        cudaMemsetAsync(p_norm, 0, NN * sizeof(float));
        k_deg<<<(EE + 255) / 256, 256>>>(d_t);
        k_degnorm<<<(NN + 255) / 256, 256>>>();

        // layer 0: h -> hhA
        cudaMemsetAsync(p_agg, 0, (size_t)NN * DD * sizeof(float));
        k_edge<<<eb, 256>>>(s_t, d_t, e_t, p_h);
        k_mma_gemm<<<gemm_blocks, 256>>>(
            p_agg, p_h, p_Bt + 0 * DD * DD, p_Bt + 1 * DD * DD, p_norm,
            p_hhA, nullptr, nullptr, nullptr, nullptr, 0, 2);

        // layer 1: hhA -> hhB
        cudaMemsetAsync(p_agg, 0, (size_t)NN * DD * sizeof(float));
        k_edge<<<eb, 256>>>(s_t, d_t, e_t, p_hhA);
        k_mma_gemm<<<gemm_blocks, 256>>>(
            p_agg, p_hhA, p_Bt + 2 * DD * DD, p_Bt + 3 * DD * DD, p_norm,
            p_hhB, nullptr, nullptr, nullptr, nullptr, 0, 2);

        // cur = l2norm(hhB)
        k_l2norm_rows<<<(NN * 32 + 255) / 256, 256>>>(p_hhB, p_hhB, NN);

        // time gate
        k_mma_gemm<<<gemm_blocks, 256>>>(
            p_h, nullptr, p_Bt + 4 * DD * DD, nullptr, nullptr,
            nullptr, bt, p_hhB, p_h, out + (size_t)t * NN * DD, 1, 1);
    }
}